// round 1
// baseline (speedup 1.0000x reference)
#include <cuda_runtime.h>

// NeRF fused render: near/far -> coarse bins -> CDF inverse sampling ->
// contraction -> alpha compositing. One warp per ray.

constexpr int T0 = 64;     // coarse intervals
constexpr int TF = 128;    // fine samples
constexpr int NEDGE = TF + 1;        // 129 fine edges
constexpr int OUTW = 4 + 3 * TF;     // 388 floats per ray
constexpr int WARPS_PER_BLOCK = 8;

__global__ __launch_bounds__(WARPS_PER_BLOCK * 32)
void nerf_render_kernel(const float* __restrict__ rays_o,
                        const float* __restrict__ rays_d,
                        const float* __restrict__ aabb,
                        const float* __restrict__ wc,     // [N, 64]
                        const float* __restrict__ sigmas, // [N, 128]
                        const float* __restrict__ rgbs,   // [N, 128, 3]
                        float* __restrict__ out,          // [N, 388]
                        int N)
{
    __shared__ float s_cdf[WARPS_PER_BLOCK][T0 + 2];      // 65 used (+pad)
    __shared__ float s_zed[WARPS_PER_BLOCK][NEDGE + 3];   // 129 used (+pad)

    const int warp = threadIdx.x >> 5;
    const int lane = threadIdx.x & 31;
    const int ray  = blockIdx.x * WARPS_PER_BLOCK + warp;
    if (ray >= N) return;

    // ---- ray + aabb ----
    const float ox = rays_o[3 * ray + 0];
    const float oy = rays_o[3 * ray + 1];
    const float oz = rays_o[3 * ray + 2];
    const float dx = rays_d[3 * ray + 0];
    const float dy = rays_d[3 * ray + 1];
    const float dz = rays_d[3 * ray + 2];

    const float ix = 1.0f / (dx + 1e-15f);
    const float iy = 1.0f / (dy + 1e-15f);
    const float iz = 1.0f / (dz + 1e-15f);
    const float t0x = (aabb[0] - ox) * ix, t1x = (aabb[3] - ox) * ix;
    const float t0y = (aabb[1] - oy) * iy, t1y = (aabb[4] - oy) * iy;
    const float t0z = (aabb[2] - oz) * iz, t1z = (aabb[5] - oz) * iz;

    float nearv = fmaxf(fmaxf(fminf(t0x, t1x), fminf(t0y, t1y)), fminf(t0z, t1z));
    float farv  = fminf(fminf(fmaxf(t0x, t1x), fmaxf(t0y, t1y)), fmaxf(t0z, t1z));
    if (farv < nearv) { nearv = 1e9f; farv = 1e9f; }
    nearv = fmaxf(nearv, 0.05f);
    const float span = farv - nearv;

    // ---- CDF of (weights + 0.01), normalized, clipped to 1 ----
    float w0 = wc[(size_t)ray * T0 + lane]      + 0.01f;
    float w1 = wc[(size_t)ray * T0 + 32 + lane] + 0.01f;

    float s0 = w0;
    #pragma unroll
    for (int o = 1; o < 32; o <<= 1) {
        float v = __shfl_up_sync(0xffffffffu, s0, o);
        if (lane >= o) s0 += v;
    }
    const float tot0 = __shfl_sync(0xffffffffu, s0, 31);
    float s1 = w1;
    #pragma unroll
    for (int o = 1; o < 32; o <<= 1) {
        float v = __shfl_up_sync(0xffffffffu, s1, o);
        if (lane >= o) s1 += v;
    }
    s1 += tot0;
    const float tot = __shfl_sync(0xffffffffu, s1, 31);
    const float inv_tot = 1.0f / tot;

    if (lane == 0) s_cdf[warp][0] = 0.0f;
    s_cdf[warp][lane + 1]  = fminf(s0 * inv_tot, 1.0f);
    s_cdf[warp][lane + 33] = fminf(s1 * inv_tot, 1.0f);
    __syncwarp();

    // ---- inverse-CDF sample 129 fine edges ----
    const float* cdfp = s_cdf[warp];
    #pragma unroll
    for (int j = lane; j < NEDGE; j += 32) {
        const float u = (j + 0.5f) * (1.0f / 129.0f);
        // searchsorted(cdf, u, side='right') over 65 entries
        int lo = 0, hi = T0 + 1;
        #pragma unroll
        for (int it = 0; it < 7; ++it) {
            if (lo < hi) {
                int mid = (lo + hi) >> 1;
                if (cdfp[mid] <= u) lo = mid + 1; else hi = mid;
            }
        }
        const int below = min(max(lo - 1, 0), T0);
        const int above = min(lo, T0);
        const float c0 = cdfp[below];
        const float c1 = cdfp[above];
        const float b0 = nearv + span * ((float)below * (1.0f / 64.0f));
        const float b1 = nearv + span * ((float)above * (1.0f / 64.0f));
        const float denom = c1 - c0;
        float t = (denom > 0.0f) ? (u - c0) / fmaxf(denom, 1e-12f) : 0.0f;
        t = fminf(fmaxf(t, 0.0f), 1.0f);
        s_zed[warp][j] = b0 + t * (b1 - b0);
    }
    __syncwarp();

    // ---- per-sample: lane owns samples [4*lane, 4*lane+4) ----
    const int i0 = lane * 4;
    const float* zedp = s_zed[warp];

    float4 sg4 = *reinterpret_cast<const float4*>(sigmas + (size_t)ray * TF + i0);
    float sg[4] = {sg4.x, sg4.y, sg4.z, sg4.w};

    float alpha[4], zm[4], lcum[4];
    float run = 1.0f;
    #pragma unroll
    for (int k = 0; k < 4; ++k) {
        const float zl = zedp[i0 + k];
        const float zr = zedp[i0 + k + 1];
        const float delta = zr - zl;
        zm[k] = 0.5f * (zl + zr);
        alpha[k] = 1.0f - expf(-sg[k] * delta);
        lcum[k] = run;                            // exclusive local transmittance
        run *= (1.0f - alpha[k] + 1e-10f);
    }

    // warp-level exclusive multiplicative scan of per-lane products
    float incl = run;
    #pragma unroll
    for (int o = 1; o < 32; o <<= 1) {
        float v = __shfl_up_sync(0xffffffffu, incl, o);
        if (lane >= o) incl *= v;
    }
    float excl = __shfl_up_sync(0xffffffffu, incl, 1);
    if (lane == 0) excl = 1.0f;

    // rgb loads: 12 contiguous floats per lane (3x float4)
    const float4* rgbp = reinterpret_cast<const float4*>(
        rgbs + (size_t)ray * TF * 3 + (size_t)i0 * 3);
    float4 r0 = rgbp[0], r1 = rgbp[1], r2 = rgbp[2];
    float rv[12] = {r0.x, r0.y, r0.z, r0.w, r1.x, r1.y, r1.z, r1.w,
                    r2.x, r2.y, r2.z, r2.w};

    float img0 = 0.0f, img1 = 0.0f, img2 = 0.0f, dep = 0.0f;
    const size_t base = (size_t)ray * OUTW;
    float* xout = out + base + 4 + (size_t)i0 * 3;

    #pragma unroll
    for (int k = 0; k < 4; ++k) {
        const float wgt = alpha[k] * excl * lcum[k];
        img0 += wgt * rv[3 * k + 0];
        img1 += wgt * rv[3 * k + 1];
        img2 += wgt * rv[3 * k + 2];
        dep  += wgt * zm[k];

        // position + contraction
        float x = fmaf(dx, zm[k], ox);
        float y = fmaf(dy, zm[k], oy);
        float z = fmaf(dz, zm[k], oz);
        const float ax = fabsf(x), ay = fabsf(y), az = fabsf(z);
        const float mag = fmaxf(ax, fmaxf(ay, az));
        float cx = x, cy = y, cz = z;
        if (mag >= 1.0f) {
            const float im = 1.0f / mag;
            const float sm = (2.0f - im) * im;
            cx = x * im; cy = y * im; cz = z * im;
            if (ax == mag)      cx = x * sm;   // first-max tie-break (argmax order x,y,z)
            else if (ay == mag) cy = y * sm;
            else                cz = z * sm;
        }
        xout[3 * k + 0] = cx;
        xout[3 * k + 1] = cy;
        xout[3 * k + 2] = cz;
    }

    // ---- warp reduction for image + depth ----
    #pragma unroll
    for (int o = 16; o > 0; o >>= 1) {
        img0 += __shfl_down_sync(0xffffffffu, img0, o);
        img1 += __shfl_down_sync(0xffffffffu, img1, o);
        img2 += __shfl_down_sync(0xffffffffu, img2, o);
        dep  += __shfl_down_sync(0xffffffffu, dep,  o);
    }
    if (lane == 0) {
        out[base + 0] = img0;
        out[base + 1] = img1;
        out[base + 2] = img2;
        out[base + 3] = dep;
    }
}

extern "C" void kernel_launch(void* const* d_in, const int* in_sizes, int n_in,
                              void* d_out, int out_size)
{
    const float* rays_o = (const float*)d_in[0];
    const float* rays_d = (const float*)d_in[1];
    const float* aabb   = (const float*)d_in[2];
    const float* wc     = (const float*)d_in[3];
    const float* sigmas = (const float*)d_in[4];
    const float* rgbs   = (const float*)d_in[5];
    float* out = (float*)d_out;

    const int N = in_sizes[0] / 3;   // rays_o has N*3 elements
    const int blocks = (N + WARPS_PER_BLOCK - 1) / WARPS_PER_BLOCK;
    nerf_render_kernel<<<blocks, WARPS_PER_BLOCK * 32>>>(
        rays_o, rays_d, aabb, wc, sigmas, rgbs, out, N);
}

// round 2
// speedup vs baseline: 1.1911x; 1.1911x over previous
#include <cuda_runtime.h>

// NeRF fused render: near/far -> coarse bins -> CDF inverse sampling ->
// contraction -> alpha compositing. One warp per ray, smem-staged I/O.

constexpr int T0 = 64;     // coarse intervals
constexpr int TF = 128;    // fine samples
constexpr int NEDGE = TF + 1;        // 129 fine edges
constexpr int OUTW = 4 + 3 * TF;     // 388 floats per ray
constexpr int WARPS_PER_BLOCK = 8;

__global__ __launch_bounds__(WARPS_PER_BLOCK * 32)
void nerf_render_kernel(const float* __restrict__ rays_o,
                        const float* __restrict__ rays_d,
                        const float* __restrict__ aabb,
                        const float* __restrict__ wc,     // [N, 64]
                        const float* __restrict__ sigmas, // [N, 128]
                        const float* __restrict__ rgbs,   // [N, 128, 3]
                        float* __restrict__ out,          // [N, 388]
                        int N)
{
    __shared__ float s_cdf[WARPS_PER_BLOCK][T0 + 2];      // 65 used (+pad)
    __shared__ float s_zed[WARPS_PER_BLOCK][NEDGE + 3];   // 129 used (+pad)
    __shared__ float s_stage[WARPS_PER_BLOCK][OUTW];      // 388: rgb in, out row out

    const int warp = threadIdx.x >> 5;
    const int lane = threadIdx.x & 31;
    const int ray  = blockIdx.x * WARPS_PER_BLOCK + warp;
    if (ray >= N) return;

    // ---- stage rgb row coalesced into smem (96 float4) ----
    {
        const float4* rgbsrc = reinterpret_cast<const float4*>(
            rgbs + (size_t)ray * TF * 3);
        float4* st4 = reinterpret_cast<float4*>(s_stage[warp]);
        st4[lane]      = rgbsrc[lane];
        st4[lane + 32] = rgbsrc[lane + 32];
        st4[lane + 64] = rgbsrc[lane + 64];
    }

    // ---- ray + aabb ----
    const float ox = rays_o[3 * ray + 0];
    const float oy = rays_o[3 * ray + 1];
    const float oz = rays_o[3 * ray + 2];
    const float dx = rays_d[3 * ray + 0];
    const float dy = rays_d[3 * ray + 1];
    const float dz = rays_d[3 * ray + 2];

    const float ix = 1.0f / (dx + 1e-15f);
    const float iy = 1.0f / (dy + 1e-15f);
    const float iz = 1.0f / (dz + 1e-15f);
    const float t0x = (aabb[0] - ox) * ix, t1x = (aabb[3] - ox) * ix;
    const float t0y = (aabb[1] - oy) * iy, t1y = (aabb[4] - oy) * iy;
    const float t0z = (aabb[2] - oz) * iz, t1z = (aabb[5] - oz) * iz;

    float nearv = fmaxf(fmaxf(fminf(t0x, t1x), fminf(t0y, t1y)), fminf(t0z, t1z));
    float farv  = fminf(fminf(fmaxf(t0x, t1x), fmaxf(t0y, t1y)), fmaxf(t0z, t1z));
    if (farv < nearv) { nearv = 1e9f; farv = 1e9f; }
    nearv = fmaxf(nearv, 0.05f);
    const float span = farv - nearv;

    // ---- CDF of (weights + 0.01), normalized, clipped to 1 ----
    float w0 = wc[(size_t)ray * T0 + lane]      + 0.01f;
    float w1 = wc[(size_t)ray * T0 + 32 + lane] + 0.01f;

    float s0 = w0;
    #pragma unroll
    for (int o = 1; o < 32; o <<= 1) {
        float v = __shfl_up_sync(0xffffffffu, s0, o);
        if (lane >= o) s0 += v;
    }
    const float tot0 = __shfl_sync(0xffffffffu, s0, 31);
    float s1 = w1;
    #pragma unroll
    for (int o = 1; o < 32; o <<= 1) {
        float v = __shfl_up_sync(0xffffffffu, s1, o);
        if (lane >= o) s1 += v;
    }
    s1 += tot0;
    const float tot = __shfl_sync(0xffffffffu, s1, 31);
    const float inv_tot = 1.0f / tot;

    if (lane == 0) s_cdf[warp][0] = 0.0f;
    s_cdf[warp][lane + 1]  = fminf(s0 * inv_tot, 1.0f);
    s_cdf[warp][lane + 33] = fminf(s1 * inv_tot, 1.0f);
    __syncwarp();

    // ---- inverse-CDF sample 129 fine edges ----
    const float* cdfp = s_cdf[warp];
    #pragma unroll
    for (int j = lane; j < NEDGE; j += 32) {
        const float u = (j + 0.5f) * (1.0f / 129.0f);
        // searchsorted(cdf, u, side='right') over 65 entries
        int lo = 0, hi = T0 + 1;
        #pragma unroll
        for (int it = 0; it < 7; ++it) {
            if (lo < hi) {
                int mid = (lo + hi) >> 1;
                if (cdfp[mid] <= u) lo = mid + 1; else hi = mid;
            }
        }
        const int below = min(max(lo - 1, 0), T0);
        const int above = min(lo, T0);
        const float c0 = cdfp[below];
        const float c1 = cdfp[above];
        const float b0 = nearv + span * ((float)below * (1.0f / 64.0f));
        const float b1 = nearv + span * ((float)above * (1.0f / 64.0f));
        const float denom = c1 - c0;
        float t = (denom > 0.0f) ? (u - c0) / fmaxf(denom, 1e-12f) : 0.0f;
        t = fminf(fmaxf(t, 0.0f), 1.0f);
        s_zed[warp][j] = b0 + t * (b1 - b0);
    }
    __syncwarp();

    // ---- per-sample: lane owns samples [4*lane, 4*lane+4) ----
    const int i0 = lane * 4;
    const float* zedp = s_zed[warp];

    float4 sg4 = *reinterpret_cast<const float4*>(sigmas + (size_t)ray * TF + i0);
    float sg[4] = {sg4.x, sg4.y, sg4.z, sg4.w};

    float alpha[4], zm[4], lcum[4];
    float run = 1.0f;
    #pragma unroll
    for (int k = 0; k < 4; ++k) {
        const float zl = zedp[i0 + k];
        const float zr = zedp[i0 + k + 1];
        const float delta = zr - zl;
        zm[k] = 0.5f * (zl + zr);
        alpha[k] = 1.0f - __expf(-sg[k] * delta);
        lcum[k] = run;                            // exclusive local transmittance
        run *= (1.0f - alpha[k] + 1e-10f);
    }

    // warp-level exclusive multiplicative scan of per-lane products
    float incl = run;
    #pragma unroll
    for (int o = 1; o < 32; o <<= 1) {
        float v = __shfl_up_sync(0xffffffffu, incl, o);
        if (lane >= o) incl *= v;
    }
    float excl = __shfl_up_sync(0xffffffffu, incl, 1);
    if (lane == 0) excl = 1.0f;

    // ---- pull rgb (12 floats) from staged smem, as 3 float4 ----
    float rv[12];
    {
        const float4* sr4 = reinterpret_cast<const float4*>(
            &s_stage[warp][(size_t)i0 * 3]);
        float4 r0 = sr4[0], r1 = sr4[1], r2 = sr4[2];
        rv[0] = r0.x; rv[1] = r0.y; rv[2]  = r0.z; rv[3]  = r0.w;
        rv[4] = r1.x; rv[5] = r1.y; rv[6]  = r1.z; rv[7]  = r1.w;
        rv[8] = r2.x; rv[9] = r2.y; rv[10] = r2.z; rv[11] = r2.w;
    }
    __syncwarp();

    float img0 = 0.0f, img1 = 0.0f, img2 = 0.0f, dep = 0.0f;
    float* xst = &s_stage[warp][4 + (size_t)i0 * 3];

    #pragma unroll
    for (int k = 0; k < 4; ++k) {
        const float wgt = alpha[k] * excl * lcum[k];
        img0 += wgt * rv[3 * k + 0];
        img1 += wgt * rv[3 * k + 1];
        img2 += wgt * rv[3 * k + 2];
        dep  += wgt * zm[k];

        // position + contraction
        float x = fmaf(dx, zm[k], ox);
        float y = fmaf(dy, zm[k], oy);
        float z = fmaf(dz, zm[k], oz);
        const float ax = fabsf(x), ay = fabsf(y), az = fabsf(z);
        const float mag = fmaxf(ax, fmaxf(ay, az));
        float cx = x, cy = y, cz = z;
        if (mag >= 1.0f) {
            const float im = 1.0f / mag;
            const float sm = (2.0f - im) * im;
            cx = x * im; cy = y * im; cz = z * im;
            if (ax == mag)      cx = x * sm;   // first-max tie-break (argmax order x,y,z)
            else if (ay == mag) cy = y * sm;
            else                cz = z * sm;
        }
        xst[3 * k + 0] = cx;
        xst[3 * k + 1] = cy;
        xst[3 * k + 2] = cz;
    }

    // ---- warp reduction for image + depth ----
    #pragma unroll
    for (int o = 16; o > 0; o >>= 1) {
        img0 += __shfl_down_sync(0xffffffffu, img0, o);
        img1 += __shfl_down_sync(0xffffffffu, img1, o);
        img2 += __shfl_down_sync(0xffffffffu, img2, o);
        dep  += __shfl_down_sync(0xffffffffu, dep,  o);
    }
    if (lane == 0) {
        s_stage[warp][0] = img0;
        s_stage[warp][1] = img1;
        s_stage[warp][2] = img2;
        s_stage[warp][3] = dep;
    }
    __syncwarp();

    // ---- coalesced store of the full 388-float output row (97 float4) ----
    {
        const float4* src4 = reinterpret_cast<const float4*>(s_stage[warp]);
        float4* dst4 = reinterpret_cast<float4*>(out + (size_t)ray * OUTW);
        dst4[lane]      = src4[lane];
        dst4[lane + 32] = src4[lane + 32];
        dst4[lane + 64] = src4[lane + 64];
        if (lane == 0) dst4[96] = src4[96];
    }
}

extern "C" void kernel_launch(void* const* d_in, const int* in_sizes, int n_in,
                              void* d_out, int out_size)
{
    const float* rays_o = (const float*)d_in[0];
    const float* rays_d = (const float*)d_in[1];
    const float* aabb   = (const float*)d_in[2];
    const float* wc     = (const float*)d_in[3];
    const float* sigmas = (const float*)d_in[4];
    const float* rgbs   = (const float*)d_in[5];
    float* out = (float*)d_out;

    const int N = in_sizes[0] / 3;   // rays_o has N*3 elements
    const int blocks = (N + WARPS_PER_BLOCK - 1) / WARPS_PER_BLOCK;
    nerf_render_kernel<<<blocks, WARPS_PER_BLOCK * 32>>>(
        rays_o, rays_d, aabb, wc, sigmas, rgbs, out, N);
}

// round 3
// speedup vs baseline: 1.2081x; 1.0143x over previous
#include <cuda_runtime.h>

// NeRF fused render: near/far -> coarse bins -> CDF inverse sampling ->
// contraction -> alpha compositing.
// One warp per ray, STRIDED sample ownership: lane l owns samples
// {l, l+32, l+64, l+96}. All global I/O is naturally coalesced; no staging.

constexpr int T0 = 64;     // coarse intervals
constexpr int TF = 128;    // fine samples
constexpr int OUTW = 4 + 3 * TF;     // 388 floats per ray
constexpr int WARPS_PER_BLOCK = 8;
constexpr unsigned FULL = 0xffffffffu;

__device__ __forceinline__ float sample_edge(const float* __restrict__ cdfp,
                                             int j, float nearv, float span)
{
    const float u = (j + 0.5f) * (1.0f / 129.0f);
    // searchsorted(cdf, u, side='right') over 65 entries
    int lo = 0, hi = T0 + 1;
    #pragma unroll
    for (int it = 0; it < 7; ++it) {
        if (lo < hi) {
            int mid = (lo + hi) >> 1;
            if (cdfp[mid] <= u) lo = mid + 1; else hi = mid;
        }
    }
    const int below = min(max(lo - 1, 0), T0);
    const int above = min(lo, T0);
    const float c0 = cdfp[below];
    const float c1 = cdfp[above];
    const float b0 = fmaf(span, (float)below * (1.0f / 64.0f), nearv);
    const float b1 = fmaf(span, (float)above * (1.0f / 64.0f), nearv);
    const float denom = c1 - c0;
    float t = (denom > 0.0f) ? (u - c0) / fmaxf(denom, 1e-12f) : 0.0f;
    t = fminf(fmaxf(t, 0.0f), 1.0f);
    return b0 + t * (b1 - b0);
}

__global__ __launch_bounds__(WARPS_PER_BLOCK * 32)
void nerf_render_kernel(const float* __restrict__ rays_o,
                        const float* __restrict__ rays_d,
                        const float* __restrict__ aabb,
                        const float* __restrict__ wc,     // [N, 64]
                        const float* __restrict__ sigmas, // [N, 128]
                        const float* __restrict__ rgbs,   // [N, 128, 3]
                        float* __restrict__ out,          // [N, 388]
                        int N)
{
    __shared__ float s_cdf[WARPS_PER_BLOCK][T0 + 4];      // 65 used (+pad)

    const int warp = threadIdx.x >> 5;
    const int lane = threadIdx.x & 31;
    const int ray  = blockIdx.x * WARPS_PER_BLOCK + warp;
    if (ray >= N) return;

    // ---- ray + aabb ----
    const float ox = rays_o[3 * ray + 0];
    const float oy = rays_o[3 * ray + 1];
    const float oz = rays_o[3 * ray + 2];
    const float dx = rays_d[3 * ray + 0];
    const float dy = rays_d[3 * ray + 1];
    const float dz = rays_d[3 * ray + 2];

    const float ix = 1.0f / (dx + 1e-15f);
    const float iy = 1.0f / (dy + 1e-15f);
    const float iz = 1.0f / (dz + 1e-15f);
    const float t0x = (aabb[0] - ox) * ix, t1x = (aabb[3] - ox) * ix;
    const float t0y = (aabb[1] - oy) * iy, t1y = (aabb[4] - oy) * iy;
    const float t0z = (aabb[2] - oz) * iz, t1z = (aabb[5] - oz) * iz;

    float nearv = fmaxf(fmaxf(fminf(t0x, t1x), fminf(t0y, t1y)), fminf(t0z, t1z));
    float farv  = fminf(fminf(fmaxf(t0x, t1x), fmaxf(t0y, t1y)), fmaxf(t0z, t1z));
    if (farv < nearv) { nearv = 1e9f; farv = 1e9f; }
    nearv = fmaxf(nearv, 0.05f);
    const float span = farv - nearv;

    // ---- CDF of (weights + 0.01), normalized, clipped to 1 ----
    float s0 = wc[(size_t)ray * T0 + lane]      + 0.01f;
    float s1 = wc[(size_t)ray * T0 + 32 + lane] + 0.01f;

    #pragma unroll
    for (int o = 1; o < 32; o <<= 1) {
        float v = __shfl_up_sync(FULL, s0, o);
        if (lane >= o) s0 += v;
    }
    s1 += __shfl_sync(FULL, s0, 31) - s0 + s0;   // keep s0; add total below
    // redo cleanly: inclusive scan of second half, then add total of first
    {
        float t = wc[(size_t)ray * T0 + 32 + lane] + 0.01f;
        #pragma unroll
        for (int o = 1; o < 32; o <<= 1) {
            float v = __shfl_up_sync(FULL, t, o);
            if (lane >= o) t += v;
        }
        s1 = t + __shfl_sync(FULL, s0, 31);
    }
    const float tot = __shfl_sync(FULL, s1, 31);
    const float inv_tot = 1.0f / tot;

    if (lane == 0) s_cdf[warp][0] = 0.0f;
    s_cdf[warp][lane + 1]  = fminf(s0 * inv_tot, 1.0f);
    s_cdf[warp][lane + 33] = fminf(s1 * inv_tot, 1.0f);
    __syncwarp();

    // ---- fine edges in registers: e[c] = edge(32c + lane), e[4] = edge(128) ----
    const float* cdfp = s_cdf[warp];
    float e[5];
    #pragma unroll
    for (int c = 0; c < 4; ++c)
        e[c] = sample_edge(cdfp, 32 * c + lane, nearv, span);
    e[4] = sample_edge(cdfp, 128, nearv, span);   // uniform across warp

    // ---- per-chunk compositing + contraction + output ----
    const float* sgp = sigmas + (size_t)ray * TF;
    const float* rgp = rgbs + (size_t)ray * TF * 3;
    const size_t base = (size_t)ray * OUTW;
    float* xoutb = out + base + 4;

    float img0 = 0.0f, img1 = 0.0f, img2 = 0.0f, dep = 0.0f;
    float carry = 1.0f;

    #pragma unroll
    for (int c = 0; c < 4; ++c) {
        const int si = 32 * c + lane;            // this lane's sample index
        const float zl = e[c];
        float zr = __shfl_sync(FULL, e[c], (lane + 1) & 31);
        const float zr31 = __shfl_sync(FULL, e[c + 1], 0);
        if (lane == 31) zr = zr31;

        const float delta = zr - zl;
        const float zm = 0.5f * (zl + zr);
        const float sg = sgp[si];
        const float alpha = 1.0f - __expf(-sg * delta);
        const float v = 1.0f - alpha + 1e-10f;

        // warp inclusive multiplicative scan of v
        float incl = v;
        #pragma unroll
        for (int o = 1; o < 32; o <<= 1) {
            float p = __shfl_up_sync(FULL, incl, o);
            if (lane >= o) incl *= p;
        }
        float excl = __shfl_up_sync(FULL, incl, 1);
        if (lane == 0) excl = 1.0f;
        const float chunk_tot = __shfl_sync(FULL, incl, 31);

        const float wgt = alpha * carry * excl;
        carry *= chunk_tot;

        // rgb: coalesced scalar loads
        const float r0 = rgp[3 * si + 0];
        const float r1 = rgp[3 * si + 1];
        const float r2 = rgp[3 * si + 2];
        img0 += wgt * r0;
        img1 += wgt * r1;
        img2 += wgt * r2;
        dep  += wgt * zm;

        // position + contraction
        float x = fmaf(dx, zm, ox);
        float y = fmaf(dy, zm, oy);
        float z = fmaf(dz, zm, oz);
        const float ax = fabsf(x), ay = fabsf(y), az = fabsf(z);
        const float mag = fmaxf(ax, fmaxf(ay, az));
        float cx = x, cy = y, cz = z;
        if (mag >= 1.0f) {
            const float im = 1.0f / mag;
            const float sm = (2.0f - im) * im;
            cx = x * im; cy = y * im; cz = z * im;
            if (ax == mag)      cx = x * sm;   // argmax tie-break order x,y,z
            else if (ay == mag) cy = y * sm;
            else                cz = z * sm;
        }
        xoutb[3 * si + 0] = cx;
        xoutb[3 * si + 1] = cy;
        xoutb[3 * si + 2] = cz;
    }

    // ---- warp reduction for image + depth ----
    #pragma unroll
    for (int o = 16; o > 0; o >>= 1) {
        img0 += __shfl_down_sync(FULL, img0, o);
        img1 += __shfl_down_sync(FULL, img1, o);
        img2 += __shfl_down_sync(FULL, img2, o);
        dep  += __shfl_down_sync(FULL, dep,  o);
    }
    if (lane == 0) {
        float4 head = make_float4(img0, img1, img2, dep);
        *reinterpret_cast<float4*>(out + base) = head;   // 1552B-aligned
    }
}

extern "C" void kernel_launch(void* const* d_in, const int* in_sizes, int n_in,
                              void* d_out, int out_size)
{
    const float* rays_o = (const float*)d_in[0];
    const float* rays_d = (const float*)d_in[1];
    const float* aabb   = (const float*)d_in[2];
    const float* wc     = (const float*)d_in[3];
    const float* sigmas = (const float*)d_in[4];
    const float* rgbs   = (const float*)d_in[5];
    float* out = (float*)d_out;

    const int N = in_sizes[0] / 3;   // rays_o has N*3 elements
    const int blocks = (N + WARPS_PER_BLOCK - 1) / WARPS_PER_BLOCK;
    nerf_render_kernel<<<blocks, WARPS_PER_BLOCK * 32>>>(
        rays_o, rays_d, aabb, wc, sigmas, rgbs, out, N);
}

// round 4
// speedup vs baseline: 1.2745x; 1.0550x over previous
#include <cuda_runtime.h>

// NeRF fused render: near/far -> coarse bins -> CDF inverse sampling ->
// contraction -> alpha compositing.
// One warp per ray, strided sample ownership: lane l owns samples
// {l, l+32, l+64, l+96}. All global I/O naturally coalesced.
// launch_bounds(256,8) -> 32 regs -> full occupancy (latency-bound kernel).

constexpr int T0 = 64;     // coarse intervals
constexpr int TF = 128;    // fine samples
constexpr int OUTW = 4 + 3 * TF;     // 388 floats per ray
constexpr int WARPS_PER_BLOCK = 8;
constexpr unsigned FULL = 0xffffffffu;

__device__ __forceinline__ float sample_edge(const float* __restrict__ cdfp,
                                             int j, float nearv, float span)
{
    const float u = (j + 0.5f) * (1.0f / 129.0f);
    // searchsorted(cdf, u, side='right') over 65 entries
    int lo = 0, hi = T0 + 1;
    #pragma unroll
    for (int it = 0; it < 7; ++it) {
        if (lo < hi) {
            int mid = (lo + hi) >> 1;
            if (cdfp[mid] <= u) lo = mid + 1; else hi = mid;
        }
    }
    const int below = min(max(lo - 1, 0), T0);
    const int above = min(lo, T0);
    const float c0 = cdfp[below];
    const float c1 = cdfp[above];
    const float b0 = fmaf(span, (float)below * (1.0f / 64.0f), nearv);
    const float b1 = fmaf(span, (float)above * (1.0f / 64.0f), nearv);
    const float denom = c1 - c0;
    float t = (denom > 0.0f) ? __fdividef(u - c0, fmaxf(denom, 1e-12f)) : 0.0f;
    t = fminf(fmaxf(t, 0.0f), 1.0f);
    return b0 + t * (b1 - b0);
}

__global__ __launch_bounds__(WARPS_PER_BLOCK * 32, 8)
void nerf_render_kernel(const float* __restrict__ rays_o,
                        const float* __restrict__ rays_d,
                        const float* __restrict__ aabb,
                        const float* __restrict__ wc,     // [N, 64]
                        const float* __restrict__ sigmas, // [N, 128]
                        const float* __restrict__ rgbs,   // [N, 128, 3]
                        float* __restrict__ out,          // [N, 388]
                        int N)
{
    __shared__ float s_cdf[WARPS_PER_BLOCK][T0 + 4];      // 65 used (+pad)

    const int warp = threadIdx.x >> 5;
    const int lane = threadIdx.x & 31;
    const int ray  = blockIdx.x * WARPS_PER_BLOCK + warp;
    if (ray >= N) return;

    // ---- ray + aabb ----
    const float ox = rays_o[3 * ray + 0];
    const float oy = rays_o[3 * ray + 1];
    const float oz = rays_o[3 * ray + 2];
    const float dx = rays_d[3 * ray + 0];
    const float dy = rays_d[3 * ray + 1];
    const float dz = rays_d[3 * ray + 2];

    const float ix = 1.0f / (dx + 1e-15f);
    const float iy = 1.0f / (dy + 1e-15f);
    const float iz = 1.0f / (dz + 1e-15f);
    const float t0x = (aabb[0] - ox) * ix, t1x = (aabb[3] - ox) * ix;
    const float t0y = (aabb[1] - oy) * iy, t1y = (aabb[4] - oy) * iy;
    const float t0z = (aabb[2] - oz) * iz, t1z = (aabb[5] - oz) * iz;

    float nearv = fmaxf(fmaxf(fminf(t0x, t1x), fminf(t0y, t1y)), fminf(t0z, t1z));
    float farv  = fminf(fminf(fmaxf(t0x, t1x), fmaxf(t0y, t1y)), fmaxf(t0z, t1z));
    if (farv < nearv) { nearv = 1e9f; farv = 1e9f; }
    nearv = fmaxf(nearv, 0.05f);
    const float span = farv - nearv;

    // ---- CDF of (weights + 0.01), normalized, clipped to 1 ----
    float s0 = wc[(size_t)ray * T0 + lane]      + 0.01f;
    float s1 = wc[(size_t)ray * T0 + 32 + lane] + 0.01f;

    #pragma unroll
    for (int o = 1; o < 32; o <<= 1) {
        float v = __shfl_up_sync(FULL, s0, o);
        if (lane >= o) s0 += v;
    }
    #pragma unroll
    for (int o = 1; o < 32; o <<= 1) {
        float v = __shfl_up_sync(FULL, s1, o);
        if (lane >= o) s1 += v;
    }
    s1 += __shfl_sync(FULL, s0, 31);
    const float inv_tot = 1.0f / __shfl_sync(FULL, s1, 31);

    if (lane == 0) s_cdf[warp][0] = 0.0f;
    s_cdf[warp][lane + 1]  = fminf(s0 * inv_tot, 1.0f);
    s_cdf[warp][lane + 33] = fminf(s1 * inv_tot, 1.0f);
    __syncwarp();

    // ---- fine edges in registers: e[c] = edge(32c + lane), e[4] = edge(128) ----
    const float* cdfp = s_cdf[warp];
    float e[5];
    #pragma unroll
    for (int c = 0; c < 4; ++c)
        e[c] = sample_edge(cdfp, 32 * c + lane, nearv, span);
    e[4] = sample_edge(cdfp, 128, nearv, span);   // uniform across warp

    // ---- per-chunk compositing + contraction + output ----
    const float* sgp = sigmas + (size_t)ray * TF;
    const float* rgp = rgbs + (size_t)ray * TF * 3;
    const size_t base = (size_t)ray * OUTW;
    float* xoutb = out + base + 4;

    float img0 = 0.0f, img1 = 0.0f, img2 = 0.0f, dep = 0.0f;
    float carry = 1.0f;

    #pragma unroll
    for (int c = 0; c < 4; ++c) {
        const int si = 32 * c + lane;            // this lane's sample index
        const float zl = e[c];
        float zr = __shfl_sync(FULL, e[c], (lane + 1) & 31);
        const float zr31 = __shfl_sync(FULL, e[c + 1], 0);
        if (lane == 31) zr = zr31;

        const float delta = zr - zl;
        const float zm = 0.5f * (zl + zr);
        const float sg = sgp[si];
        const float alpha = 1.0f - __expf(-sg * delta);
        const float v = 1.0f - alpha + 1e-10f;

        // warp inclusive multiplicative scan of v
        float incl = v;
        #pragma unroll
        for (int o = 1; o < 32; o <<= 1) {
            float p = __shfl_up_sync(FULL, incl, o);
            if (lane >= o) incl *= p;
        }
        float excl = __shfl_up_sync(FULL, incl, 1);
        if (lane == 0) excl = 1.0f;
        const float chunk_tot = __shfl_sync(FULL, incl, 31);

        const float wgt = alpha * carry * excl;
        carry *= chunk_tot;

        // rgb: coalesced scalar loads (stride-3 across lanes, 3 lines/instr)
        const float r0 = rgp[3 * si + 0];
        const float r1 = rgp[3 * si + 1];
        const float r2 = rgp[3 * si + 2];
        img0 += wgt * r0;
        img1 += wgt * r1;
        img2 += wgt * r2;
        dep  += wgt * zm;

        // position + contraction
        float x = fmaf(dx, zm, ox);
        float y = fmaf(dy, zm, oy);
        float z = fmaf(dz, zm, oz);
        const float ax = fabsf(x), ay = fabsf(y), az = fabsf(z);
        const float mag = fmaxf(ax, fmaxf(ay, az));
        float cx = x, cy = y, cz = z;
        if (mag >= 1.0f) {
            const float im = 1.0f / mag;
            const float sm = (2.0f - im) * im;
            cx = x * im; cy = y * im; cz = z * im;
            if (ax == mag)      cx = x * sm;   // argmax tie-break order x,y,z
            else if (ay == mag) cy = y * sm;
            else                cz = z * sm;
        }
        xoutb[3 * si + 0] = cx;
        xoutb[3 * si + 1] = cy;
        xoutb[3 * si + 2] = cz;
    }

    // ---- warp reduction for image + depth ----
    #pragma unroll
    for (int o = 16; o > 0; o >>= 1) {
        img0 += __shfl_down_sync(FULL, img0, o);
        img1 += __shfl_down_sync(FULL, img1, o);
        img2 += __shfl_down_sync(FULL, img2, o);
        dep  += __shfl_down_sync(FULL, dep,  o);
    }
    if (lane == 0) {
        float4 head = make_float4(img0, img1, img2, dep);
        *reinterpret_cast<float4*>(out + base) = head;   // 1552B rows, 16B aligned
    }
}

extern "C" void kernel_launch(void* const* d_in, const int* in_sizes, int n_in,
                              void* d_out, int out_size)
{
    const float* rays_o = (const float*)d_in[0];
    const float* rays_d = (const float*)d_in[1];
    const float* aabb   = (const float*)d_in[2];
    const float* wc     = (const float*)d_in[3];
    const float* sigmas = (const float*)d_in[4];
    const float* rgbs   = (const float*)d_in[5];
    float* out = (float*)d_out;

    const int N = in_sizes[0] / 3;   // rays_o has N*3 elements
    const int blocks = (N + WARPS_PER_BLOCK - 1) / WARPS_PER_BLOCK;
    nerf_render_kernel<<<blocks, WARPS_PER_BLOCK * 32>>>(
        rays_o, rays_d, aabb, wc, sigmas, rgbs, out, N);
}

// round 5
// speedup vs baseline: 1.6081x; 1.2618x over previous
#include <cuda_runtime.h>

// NeRF fused render: near/far -> coarse bins -> CDF inverse sampling ->
// contraction -> alpha compositing.
// One warp per ray, strided sample ownership (lane l owns samples l+32c).
// Inverse-CDF sampling done by SCATTER: each lane owns 2 CDF intervals and
// computes in closed form which of the 129 uniform u's land in them, writing
// z-edges straight to smem. No binary search, no dependent-LDS chains.

constexpr int T0 = 64;     // coarse intervals
constexpr int TF = 128;    // fine samples
constexpr int OUTW = 4 + 3 * TF;     // 388 floats per ray
constexpr int WARPS_PER_BLOCK = 8;
constexpr unsigned FULL = 0xffffffffu;

__global__ __launch_bounds__(WARPS_PER_BLOCK * 32, 8)
void nerf_render_kernel(const float* __restrict__ rays_o,
                        const float* __restrict__ rays_d,
                        const float* __restrict__ aabb,
                        const float* __restrict__ wc,     // [N, 64]
                        const float* __restrict__ sigmas, // [N, 128]
                        const float* __restrict__ rgbs,   // [N, 128, 3]
                        float* __restrict__ out,          // [N, 388]
                        int N)
{
    __shared__ float s_zed[WARPS_PER_BLOCK][TF + 4];      // 129 used (+pad)

    const int warp = threadIdx.x >> 5;
    const int lane = threadIdx.x & 31;
    const int ray  = blockIdx.x * WARPS_PER_BLOCK + warp;
    if (ray >= N) return;

    // ---- ray + aabb ----
    const float ox = rays_o[3 * ray + 0];
    const float oy = rays_o[3 * ray + 1];
    const float oz = rays_o[3 * ray + 2];
    const float dx = rays_d[3 * ray + 0];
    const float dy = rays_d[3 * ray + 1];
    const float dz = rays_d[3 * ray + 2];

    const float ix = 1.0f / (dx + 1e-15f);
    const float iy = 1.0f / (dy + 1e-15f);
    const float iz = 1.0f / (dz + 1e-15f);
    const float t0x = (aabb[0] - ox) * ix, t1x = (aabb[3] - ox) * ix;
    const float t0y = (aabb[1] - oy) * iy, t1y = (aabb[4] - oy) * iy;
    const float t0z = (aabb[2] - oz) * iz, t1z = (aabb[5] - oz) * iz;

    float nearv = fmaxf(fmaxf(fminf(t0x, t1x), fminf(t0y, t1y)), fminf(t0z, t1z));
    float farv  = fminf(fminf(fmaxf(t0x, t1x), fmaxf(t0y, t1y)), fmaxf(t0z, t1z));
    if (farv < nearv) { nearv = 1e9f; farv = 1e9f; }
    nearv = fmaxf(nearv, 0.05f);
    const float span = farv - nearv;
    const float db = span * (1.0f / 64.0f);   // coarse bin width (b1-b0, constant)

    // ---- CDF of (weights + 0.01), normalized, clipped to 1 (registers only) ----
    float s0 = wc[(size_t)ray * T0 + lane]      + 0.01f;
    float s1 = wc[(size_t)ray * T0 + 32 + lane] + 0.01f;

    #pragma unroll
    for (int o = 1; o < 32; o <<= 1) {
        float v = __shfl_up_sync(FULL, s0, o);
        if (lane >= o) s0 += v;
    }
    #pragma unroll
    for (int o = 1; o < 32; o <<= 1) {
        float v = __shfl_up_sync(FULL, s1, o);
        if (lane >= o) s1 += v;
    }
    s1 += __shfl_sync(FULL, s0, 31);
    const float inv_tot = 1.0f / __shfl_sync(FULL, s1, 31);

    // lane l holds C[l+1] = ca and C[l+33] = cb  (C[0] = 0)
    const float ca = fminf(s0 * inv_tot, 1.0f);
    const float cb = fminf(s1 * inv_tot, 1.0f);
    const float ca_up = __shfl_up_sync(FULL, ca, 1);
    const float cb_up = __shfl_up_sync(FULL, cb, 1);
    const float ca31  = __shfl_sync(FULL, ca, 31);

    float* zed = s_zed[warp];

    // ---- scatter fine edges: interval k covers u in [C[k], C[k+1]) ----
    // u_j = (j+0.5)/129  ->  j in [ceil(129*c0-0.5), ceil(129*c1-0.5))
    #pragma unroll
    for (int h = 0; h < 2; ++h) {
        const int k = h * 32 + lane;
        const float c0 = (h == 0) ? ((lane == 0) ? 0.0f : ca_up)
                                  : ((lane == 0) ? ca31 : cb_up);
        const float c1 = (h == 0) ? ca : cb;

        int j0 = (int)ceilf(fmaf(129.0f, c0, -0.5f));
        int j1 = (k == 63) ? 129 : (int)ceilf(fmaf(129.0f, c1, -0.5f));
        j0 = max(j0, 0);
        j1 = min(j1, 129);

        const float inv_den = __fdividef(1.0f, fmaxf(c1 - c0, 1e-12f));
        const float b0 = fmaf(db, (float)k, nearv);

        for (int j = j0; j < j1; ++j) {
            const float u = (j + 0.5f) * (1.0f / 129.0f);
            float t = fminf(fmaxf((u - c0) * inv_den, 0.0f), 1.0f);
            zed[j] = fmaf(t, db, b0);
        }
    }
    __syncwarp();

    // ---- per-chunk compositing + contraction + output ----
    const float* sgp = sigmas + (size_t)ray * TF;
    const float* rgp = rgbs + (size_t)ray * TF * 3;
    const size_t base = (size_t)ray * OUTW;
    float* xoutb = out + base + 4;

    float img0 = 0.0f, img1 = 0.0f, img2 = 0.0f, dep = 0.0f;
    float carry = 1.0f;

    #pragma unroll
    for (int c = 0; c < 4; ++c) {
        const int si = 32 * c + lane;            // this lane's sample index
        const float zl = zed[si];
        const float zr = zed[si + 1];

        const float delta = zr - zl;
        const float zm = 0.5f * (zl + zr);
        const float sg = sgp[si];
        const float alpha = 1.0f - __expf(-sg * delta);
        const float v = 1.0f - alpha + 1e-10f;

        // warp inclusive multiplicative scan of v
        float incl = v;
        #pragma unroll
        for (int o = 1; o < 32; o <<= 1) {
            float p = __shfl_up_sync(FULL, incl, o);
            if (lane >= o) incl *= p;
        }
        float excl = __shfl_up_sync(FULL, incl, 1);
        if (lane == 0) excl = 1.0f;
        const float chunk_tot = __shfl_sync(FULL, incl, 31);

        const float wgt = alpha * carry * excl;
        carry *= chunk_tot;

        // rgb: coalesced scalar loads (stride-3 across lanes, 3 lines/instr)
        img0 += wgt * rgp[3 * si + 0];
        img1 += wgt * rgp[3 * si + 1];
        img2 += wgt * rgp[3 * si + 2];
        dep  += wgt * zm;

        // position + contraction
        float x = fmaf(dx, zm, ox);
        float y = fmaf(dy, zm, oy);
        float z = fmaf(dz, zm, oz);
        const float ax = fabsf(x), ay = fabsf(y), az = fabsf(z);
        const float mag = fmaxf(ax, fmaxf(ay, az));
        float cx = x, cy = y, cz = z;
        if (mag >= 1.0f) {
            const float im = 1.0f / mag;
            const float sm = (2.0f - im) * im;
            cx = x * im; cy = y * im; cz = z * im;
            if (ax == mag)      cx = x * sm;   // argmax tie-break order x,y,z
            else if (ay == mag) cy = y * sm;
            else                cz = z * sm;
        }
        xoutb[3 * si + 0] = cx;
        xoutb[3 * si + 1] = cy;
        xoutb[3 * si + 2] = cz;
    }

    // ---- warp reduction for image + depth ----
    #pragma unroll
    for (int o = 16; o > 0; o >>= 1) {
        img0 += __shfl_down_sync(FULL, img0, o);
        img1 += __shfl_down_sync(FULL, img1, o);
        img2 += __shfl_down_sync(FULL, img2, o);
        dep  += __shfl_down_sync(FULL, dep,  o);
    }
    if (lane == 0) {
        float4 head = make_float4(img0, img1, img2, dep);
        *reinterpret_cast<float4*>(out + base) = head;   // 1552B rows, 16B aligned
    }
}

extern "C" void kernel_launch(void* const* d_in, const int* in_sizes, int n_in,
                              void* d_out, int out_size)
{
    const float* rays_o = (const float*)d_in[0];
    const float* rays_d = (const float*)d_in[1];
    const float* aabb   = (const float*)d_in[2];
    const float* wc     = (const float*)d_in[3];
    const float* sigmas = (const float*)d_in[4];
    const float* rgbs   = (const float*)d_in[5];
    float* out = (float*)d_out;

    const int N = in_sizes[0] / 3;   // rays_o has N*3 elements
    const int blocks = (N + WARPS_PER_BLOCK - 1) / WARPS_PER_BLOCK;
    nerf_render_kernel<<<blocks, WARPS_PER_BLOCK * 32>>>(
        rays_o, rays_d, aabb, wc, sigmas, rgbs, out, N);
}